// round 6
// baseline (speedup 1.0000x reference)
#include <cuda_runtime.h>
#include <cuda_bf16.h>
#include <cstdint>
#include <cmath>

// Problem constants
constexpr int Nn  = 2048;   // tokens
constexpr int Dk  = 1024;   // model dim
constexpr int Hh  = 16;     // q heads
constexpr int KVh = 4;      // kv heads
constexpr int DHd = 64;     // head dim
constexpr int Ee  = 8;      // experts
constexpr int Ff  = 2048;   // ffn dim
constexpr int CHc = 64;     // ctrl hidden
constexpr float EPS = 1e-6f;
constexpr float DT  = 0.1f;
constexpr float BASE_SCALE = 10.0f;

// ---------------- device scratch (static, allowed) ----------------
__device__ float g_h1[Nn * Dk];
__device__ float g_q[Nn * Hh * DHd];
__device__ float g_k[Nn * KVh * DHd];
__device__ float g_v[Nn * KVh * DHd];
__device__ float g_o[Nn * Hh * DHd];
__device__ float g_oproj[Nn * Dk];
__device__ float g_ctrl[Nn * CHc];
__device__ float g_co[Nn * 3 * Dk];
__device__ float g_hidden2[Nn * Dk];
__device__ float g_x2[Nn * Dk];
__device__ float g_mid[Nn * Ff];
__device__ int   g_counts[Ee];
__device__ int   g_list[Ee * Nn];

// ---------------- rmsnorm (float4 vectorized) ----------------
__global__ void rmsnorm_kernel(const float* __restrict__ x, const float* __restrict__ w,
                               float* __restrict__ y)
{
    int n = blockIdx.x;
    const float4* xr = (const float4*)(x + (size_t)n * Dk);
    const float4* wr = (const float4*)w;
    float4*       yr = (float4*)(y + (size_t)n * Dk);
    float s = 0.f;
    float4 v = xr[threadIdx.x];   // Dk/4 = 256 float4, 256 threads
    s = v.x * v.x + v.y * v.y + v.z * v.z + v.w * v.w;
    __shared__ float red[8];
    int lane = threadIdx.x & 31, wid = threadIdx.x >> 5;
    #pragma unroll
    for (int o = 16; o; o >>= 1) s += __shfl_xor_sync(0xffffffffu, s, o);
    if (lane == 0) red[wid] = s;
    __syncthreads();
    if (wid == 0) {
        float t = (lane < 8) ? red[lane] : 0.f;
        #pragma unroll
        for (int o = 4; o; o >>= 1) t += __shfl_xor_sync(0xffffffffu, t, o);
        if (lane == 0) red[0] = rsqrtf(t / Dk + EPS);
    }
    __syncthreads();
    float rms = red[0];
    float4 wv = wr[threadIdx.x];
    float4 out;
    out.x = v.x * rms * wv.x;
    out.y = v.y * rms * wv.y;
    out.z = v.z * rms * wv.z;
    out.w = v.w * rms * wv.w;
    yr[threadIdx.x] = out;
}

// ---------------- generic tiled SGEMM ----------------
// C[M,N] = act( A@B (+ A2@B2) + bias )
// BM=BN=64, BK=16, 256 threads, 4x4 per thread. All dims divisible.
template<int ACT, bool DUAL>
__global__ void gemm_kernel(const float* __restrict__ A, const float* __restrict__ B,
                            const float* __restrict__ A2, const float* __restrict__ B2,
                            const float* __restrict__ bias, float* __restrict__ C,
                            int M, int N, int K)
{
    __shared__ float As[64][16];
    __shared__ float Bs[16][64];
    int tid = threadIdx.x;
    int tx = tid & 15, ty = tid >> 4;
    int row0 = blockIdx.y * 64, col0 = blockIdx.x * 64;
    float acc[4][4] = {};

    int npass = DUAL ? 2 : 1;
    for (int pass = 0; pass < npass; ++pass) {
        const float* Ap = pass ? A2 : A;
        const float* Bp = pass ? B2 : B;
        for (int k0 = 0; k0 < K; k0 += 16) {
            #pragma unroll
            for (int i = tid; i < 64 * 16; i += 256) {
                int r = i >> 4, c = i & 15;
                As[r][c] = Ap[(size_t)(row0 + r) * K + k0 + c];
            }
            #pragma unroll
            for (int i = tid; i < 16 * 64; i += 256) {
                int r = i >> 6, c = i & 63;
                Bs[r][c] = Bp[(size_t)(k0 + r) * N + col0 + c];
            }
            __syncthreads();
            #pragma unroll
            for (int kk = 0; kk < 16; ++kk) {
                float a[4], b[4];
                #pragma unroll
                for (int i = 0; i < 4; i++) a[i] = As[ty * 4 + i][kk];
                #pragma unroll
                for (int j = 0; j < 4; j++) b[j] = Bs[kk][tx * 4 + j];
                #pragma unroll
                for (int i = 0; i < 4; i++)
                    #pragma unroll
                    for (int j = 0; j < 4; j++)
                        acc[i][j] += a[i] * b[j];
            }
            __syncthreads();
        }
    }
    #pragma unroll
    for (int i = 0; i < 4; i++) {
        int r = row0 + ty * 4 + i;
        #pragma unroll
        for (int j = 0; j < 4; j++) {
            int c = col0 + tx * 4 + j;
            float v = acc[i][j];
            if (bias) v += bias[c];
            if (ACT == 1) v = v / (1.f + expf(-v));   // silu
            C[(size_t)r * N + c] = v;
        }
    }
}

// ---------------- q/k rmsnorm + rope ----------------
__global__ void qknorm_rope_kernel(float* __restrict__ q, float* __restrict__ k,
                                   const int* __restrict__ positions,
                                   const float* __restrict__ qw, const float* __restrict__ kw)
{
    int n = blockIdx.x;
    int hh = blockIdx.y;   // 0..H+KV-1
    float* x; const float* w;
    if (hh < Hh) { x = q + ((size_t)n * Hh + hh) * DHd; w = qw; }
    else         { x = k + ((size_t)n * KVh + (hh - Hh)) * DHd; w = kw; }
    int lane = threadIdx.x;  // 0..31
    float x1 = x[lane], x2 = x[lane + 32];
    float s = x1 * x1 + x2 * x2;
    #pragma unroll
    for (int o = 16; o; o >>= 1) s += __shfl_xor_sync(0xffffffffu, s, o);
    float rms = rsqrtf(s / 64.f + EPS);
    float v1 = x1 * rms * w[lane];
    float v2 = x2 * rms * w[lane + 32];
    // inv_freq = 10000^(-2*lane/64), computed in double for accuracy
    float inv = (float)exp(-(2.0 * (double)lane / 64.0) * log(10000.0));
    float ang = (float)positions[n] * inv;
    float c = cosf(ang), sn = sinf(ang);
    x[lane]      = v1 * c - v2 * sn;
    x[lane + 32] = v2 * c + v1 * sn;
}

// ---------------- flash-style attention (fp32, static smem <=48KB) ----------------
// BM=32 q rows per block, 64-key tiles. K and V share one smem buffer:
// load K -> scores -> softmax -> load V (same buffer) -> PV.
__global__ void attn_kernel(const float* __restrict__ q, const float* __restrict__ k,
                            const float* __restrict__ v, float* __restrict__ o)
{
    __shared__ float Qs[32][64];     //  8 KB
    __shared__ float KVs[64][65];    // 16.6 KB (shared by K then V)
    __shared__ float Ss[32][65];     //  8.3 KB
    __shared__ float mrow[32], lrow[32], crow[32];

    int h = blockIdx.y;
    int kvh = h >> 2;          // H/KV = 4
    int q0 = blockIdx.x * 32;
    int tid = threadIdx.x;
    int tx = tid & 63, ty = tid >> 6;   // tx: 0..63 (head dim / key), ty: 0..3

    for (int r = ty; r < 32; r += 4)
        Qs[r][tx] = q[((size_t)(q0 + r) * Hh + h) * DHd + tx];
    if (tid < 32) { mrow[tid] = -1e30f; lrow[tid] = 0.f; }
    float acc[8];
    #pragma unroll
    for (int i = 0; i < 8; i++) acc[i] = 0.f;
    __syncthreads();

    for (int kt = 0; kt < Nn / 64; ++kt) {
        int kb = kt * 64;
        // K tile
        for (int r = ty; r < 64; r += 4)
            KVs[r][tx] = k[((size_t)(kb + r) * KVh + kvh) * DHd + tx];
        __syncthreads();
        // scores: each thread does rows r = ty + 4*i, key column tx
        #pragma unroll
        for (int i = 0; i < 8; ++i) {
            int r = ty + i * 4;
            float s = 0.f;
            #pragma unroll
            for (int d = 0; d < 64; ++d) s += Qs[r][d] * KVs[tx][d];
            Ss[r][tx] = s * 0.125f;   // 1/sqrt(64)
        }
        __syncthreads();
        // online softmax per row
        if (tid < 32) {
            int r = tid;
            float mx = -1e30f;
            #pragma unroll 8
            for (int c = 0; c < 64; ++c) mx = fmaxf(mx, Ss[r][c]);
            float mnew = fmaxf(mrow[r], mx);
            float corr = expf(mrow[r] - mnew);
            float lsum = 0.f;
            #pragma unroll 8
            for (int c = 0; c < 64; ++c) {
                float p = expf(Ss[r][c] - mnew);
                Ss[r][c] = p; lsum += p;
            }
            lrow[r] = lrow[r] * corr + lsum;
            mrow[r] = mnew;
            crow[r] = corr;
        }
        __syncthreads();
        // V tile (reuse KVs)
        for (int r = ty; r < 64; r += 4)
            KVs[r][tx] = v[((size_t)(kb + r) * KVh + kvh) * DHd + tx];
        __syncthreads();
        // PV
        #pragma unroll
        for (int i = 0; i < 8; ++i) {
            int r = ty + i * 4;
            float s = 0.f;
            #pragma unroll
            for (int c = 0; c < 64; ++c) s += Ss[r][c] * KVs[c][tx];
            acc[i] = acc[i] * crow[r] + s;
        }
        __syncthreads();
    }
    #pragma unroll
    for (int i = 0; i < 8; ++i) {
        int r = ty + i * 4;
        o[((size_t)(q0 + r) * Hh + h) * DHd + tx] = acc[i] / lrow[r];
    }
}

// ---------------- dynamics (elementwise, float4) ----------------
__global__ void dynamics_kernel(const float4* __restrict__ hidden_in,
                                const float4* __restrict__ velocity,
                                const float4* __restrict__ oproj,
                                const float4* __restrict__ mu,
                                const float* __restrict__ co,
                                float4* __restrict__ v_out,
                                float4* __restrict__ hidden2)
{
    int idx = blockIdx.x * blockDim.x + threadIdx.x;   // float4 index
    if (idx >= Nn * Dk / 4) return;
    int n = idx / (Dk / 4), c4 = idx - n * (Dk / 4);
    const float4* cr = (const float4*)(co + (size_t)n * 3 * Dk);
    float4 a_raw  = cr[c4];
    float4 b_raw  = cr[Dk / 4 + c4];
    float4 gt_raw = cr[2 * Dk / 4 + c4];
    float4 ov  = oproj[idx];
    float4 muv = mu[idx];
    float4 vel = velocity[idx];
    float4 hin = hidden_in[idx];
    float4 vn, h2;
    #pragma unroll
    for (int j = 0; j < 4; ++j) {
        float ar = (&a_raw.x)[j], br = (&b_raw.x)[j], gr = (&gt_raw.x)[j];
        float alpha = 1.f / (1.f + expf(-ar));
        float sp = (br > 20.f) ? br : log1pf(expf(br));
        float beta = fminf(sp, 2.f);
        float gate = 1.f / (1.f + expf(-gr));
        float o = (&ov.x)[j];
        float err = o - (&muv.x)[j];
        float vv = alpha * (&vel.x)[j] - beta * err;
        vv = fminf(fmaxf(vv, -10.f), 10.f);
        (&vn.x)[j] = vv;
        (&h2.x)[j] = (&hin.x)[j] + o + DT * gate * vv;
    }
    v_out[idx] = vn;
    hidden2[idx] = h2;
}

// ---------------- router ----------------
__global__ void reset_counts_kernel()
{
    if (threadIdx.x < Ee) g_counts[threadIdx.x] = 0;
}

__global__ void router_kernel(const float* __restrict__ mu, const float* __restrict__ W,
                              const int* __restrict__ token_ids)
{
    int gwarp = (blockIdx.x * blockDim.x + threadIdx.x) >> 5;
    int lane = threadIdx.x & 31;
    if (gwarp >= Nn) return;
    float acc[Ee] = {};
    const float* m = mu + (size_t)gwarp * Dk;
    for (int d = lane; d < Dk; d += 32) {
        float mv = m[d];
        #pragma unroll
        for (int e = 0; e < Ee; ++e) acc[e] += mv * W[d * Ee + e];
    }
    #pragma unroll
    for (int o = 16; o; o >>= 1)
        #pragma unroll
        for (int e = 0; e < Ee; ++e) acc[e] += __shfl_xor_sync(0xffffffffu, acc[e], o);
    if (lane == 0) {
        int base = token_ids[gwarp] % Ee;
        int best = 0; float bv = -1e30f;
        #pragma unroll
        for (int e = 0; e < Ee; ++e) {
            float vv = acc[e] + (e == base ? BASE_SCALE : 0.f);
            if (vv > bv) { bv = vv; best = e; }   // strict > keeps first max
        }
        int pos = atomicAdd(&g_counts[best], 1);
        g_list[best * Nn + pos] = gwarp;
    }
}

// ---------------- MoE gate/up fused (gathered) ----------------
__global__ void moe_gateup_kernel(const float* __restrict__ X,
                                  const float* __restrict__ Wg,
                                  const float* __restrict__ Wu,
                                  float* __restrict__ Mid)
{
    int e = blockIdx.z;
    int cnt = g_counts[e];
    int row0 = blockIdx.y * 64;
    if (row0 >= cnt) return;
    int col0 = blockIdx.x * 64;
    const float* Bg = Wg + (size_t)e * Dk * Ff;
    const float* Bu = Wu + (size_t)e * Dk * Ff;

    __shared__ float As[64][16];
    __shared__ float Bsg[16][64];
    __shared__ float Bsu[16][64];
    __shared__ int toks[64];
    int tid = threadIdx.x;
    int tx = tid & 15, ty = tid >> 4;
    for (int i = tid; i < 64; i += 256)
        toks[i] = (row0 + i < cnt) ? g_list[e * Nn + row0 + i] : -1;
    __syncthreads();

    float accg[4][4] = {}, accu[4][4] = {};
    for (int k0 = 0; k0 < Dk; k0 += 16) {
        #pragma unroll
        for (int i = tid; i < 64 * 16; i += 256) {
            int r = i >> 4, c = i & 15;
            int t = toks[r];
            As[r][c] = (t >= 0) ? X[(size_t)t * Dk + k0 + c] : 0.f;
        }
        #pragma unroll
        for (int i = tid; i < 16 * 64; i += 256) {
            int r = i >> 6, c = i & 63;
            Bsg[r][c] = Bg[(size_t)(k0 + r) * Ff + col0 + c];
            Bsu[r][c] = Bu[(size_t)(k0 + r) * Ff + col0 + c];
        }
        __syncthreads();
        #pragma unroll
        for (int kk = 0; kk < 16; ++kk) {
            float a[4], bg[4], bu[4];
            #pragma unroll
            for (int i = 0; i < 4; i++) a[i] = As[ty * 4 + i][kk];
            #pragma unroll
            for (int j = 0; j < 4; j++) { bg[j] = Bsg[kk][tx * 4 + j]; bu[j] = Bsu[kk][tx * 4 + j]; }
            #pragma unroll
            for (int i = 0; i < 4; i++)
                #pragma unroll
                for (int j = 0; j < 4; j++) {
                    accg[i][j] += a[i] * bg[j];
                    accu[i][j] += a[i] * bu[j];
                }
        }
        __syncthreads();
    }
    #pragma unroll
    for (int i = 0; i < 4; i++) {
        int t = toks[ty * 4 + i];
        if (t < 0) continue;
        #pragma unroll
        for (int j = 0; j < 4; j++) {
            int c = col0 + tx * 4 + j;
            float g = accg[i][j];
            float sg = g / (1.f + expf(-g));
            Mid[(size_t)t * Ff + c] = sg * accu[i][j];
        }
    }
}

// ---------------- MoE down (gathered) + residual ----------------
__global__ void moe_down_kernel(const float* __restrict__ Mid,
                                const float* __restrict__ Wd,
                                const float* __restrict__ res,
                                float* __restrict__ Out)
{
    int e = blockIdx.z;
    int cnt = g_counts[e];
    int row0 = blockIdx.y * 64;
    if (row0 >= cnt) return;
    int col0 = blockIdx.x * 64;
    const float* Bp = Wd + (size_t)e * Ff * Dk;

    __shared__ float As[64][16];
    __shared__ float Bs[16][64];
    __shared__ int toks[64];
    int tid = threadIdx.x;
    int tx = tid & 15, ty = tid >> 4;
    for (int i = tid; i < 64; i += 256)
        toks[i] = (row0 + i < cnt) ? g_list[e * Nn + row0 + i] : -1;
    __syncthreads();

    float acc[4][4] = {};
    for (int k0 = 0; k0 < Ff; k0 += 16) {
        #pragma unroll
        for (int i = tid; i < 64 * 16; i += 256) {
            int r = i >> 4, c = i & 15;
            int t = toks[r];
            As[r][c] = (t >= 0) ? Mid[(size_t)t * Ff + k0 + c] : 0.f;
        }
        #pragma unroll
        for (int i = tid; i < 16 * 64; i += 256) {
            int r = i >> 6, c = i & 63;
            Bs[r][c] = Bp[(size_t)(k0 + r) * Dk + col0 + c];
        }
        __syncthreads();
        #pragma unroll
        for (int kk = 0; kk < 16; ++kk) {
            float a[4], b[4];
            #pragma unroll
            for (int i = 0; i < 4; i++) a[i] = As[ty * 4 + i][kk];
            #pragma unroll
            for (int j = 0; j < 4; j++) b[j] = Bs[kk][tx * 4 + j];
            #pragma unroll
            for (int i = 0; i < 4; i++)
                #pragma unroll
                for (int j = 0; j < 4; j++)
                    acc[i][j] += a[i] * b[j];
        }
        __syncthreads();
    }
    #pragma unroll
    for (int i = 0; i < 4; i++) {
        int t = toks[ty * 4 + i];
        if (t < 0) continue;
        #pragma unroll
        for (int j = 0; j < 4; j++) {
            int c = col0 + tx * 4 + j;
            Out[(size_t)t * Dk + c] = res[(size_t)t * Dk + c] + acc[i][j];
        }
    }
}

// ---------------- launch ----------------
static float* sym(const void* s)
{
    void* p = nullptr;
    cudaGetSymbolAddress(&p, s);
    return (float*)p;
}

extern "C" void kernel_launch(void* const* d_in, const int* in_sizes, int n_in,
                              void* d_out, int out_size)
{
    const float* hidden        = (const float*)d_in[0];
    const int*   positions     = (const int*)  d_in[1];
    const float* velocity      = (const float*)d_in[2];
    const int*   token_ids     = (const int*)  d_in[3];
    const float* mu_prev       = (const float*)d_in[4];
    const float* ln1_w         = (const float*)d_in[5];
    const float* ln2_w         = (const float*)d_in[6];
    const float* wq            = (const float*)d_in[7];
    const float* wk            = (const float*)d_in[8];
    const float* wv            = (const float*)d_in[9];
    const float* wo            = (const float*)d_in[10];
    const float* w_mu_q        = (const float*)d_in[11];
    const float* w_mu_k        = (const float*)d_in[12];
    const float* w_mu_v        = (const float*)d_in[13];
    const float* qnorm_w       = (const float*)d_in[14];
    const float* knorm_w       = (const float*)d_in[15];
    const float* dyn_mu        = (const float*)d_in[16];
    const float* dyn_mu_proj_w = (const float*)d_in[17];
    const float* ctrl_in_w     = (const float*)d_in[18];
    const float* ctrl_in_b     = (const float*)d_in[19];
    const float* ctrl_out_w    = (const float*)d_in[20];
    const float* ctrl_out_b    = (const float*)d_in[21];
    const float* mu_router_w   = (const float*)d_in[22];
    const float* w_gate        = (const float*)d_in[23];
    const float* w_up          = (const float*)d_in[24];
    const float* w_down        = (const float*)d_in[25];

    float* out_hidden = (float*)d_out;
    float* out_v      = out_hidden + (size_t)Nn * Dk;
    float* out_mu     = out_v + (size_t)Nn * Dk;

    float* h1   = sym(g_h1);
    float* qb   = sym(g_q);
    float* kb   = sym(g_k);
    float* vb   = sym(g_v);
    float* ob   = sym(g_o);
    float* op   = sym(g_oproj);
    float* ctrl = sym(g_ctrl);
    float* co   = sym(g_co);
    float* h2   = sym(g_hidden2);
    float* x2   = sym(g_x2);
    float* mid  = sym(g_mid);

    // 1) rmsnorm1
    rmsnorm_kernel<<<Nn, 256>>>(hidden, ln1_w, h1);

    // 2) QKV = h1@W + mu_prev@W_mu
    gemm_kernel<0, true><<<dim3(Hh * DHd / 64, Nn / 64), 256>>>(h1, wq, mu_prev, w_mu_q, nullptr, qb, Nn, Hh * DHd, Dk);
    gemm_kernel<0, true><<<dim3(KVh * DHd / 64, Nn / 64), 256>>>(h1, wk, mu_prev, w_mu_k, nullptr, kb, Nn, KVh * DHd, Dk);
    gemm_kernel<0, true><<<dim3(KVh * DHd / 64, Nn / 64), 256>>>(h1, wv, mu_prev, w_mu_v, nullptr, vb, Nn, KVh * DHd, Dk);

    // 3) q/k norm + rope (in place)
    qknorm_rope_kernel<<<dim3(Nn, Hh + KVh), 32>>>(qb, kb, positions, qnorm_w, knorm_w);

    // 4) attention (static smem, 32-row q tiles)
    attn_kernel<<<dim3(Nn / 32, Hh), 256>>>(qb, kb, vb, ob);

    // 5) o-proj
    gemm_kernel<0, false><<<dim3(Dk / 64, Nn / 64), 256>>>(ob, wo, nullptr, nullptr, nullptr, op, Nn, Dk, Hh * DHd);

    // 6) mu_cur = dyn_mu + oproj @ dyn_mu_proj_w   (written directly to output slice)
    gemm_kernel<0, false><<<dim3(Dk / 64, Nn / 64), 256>>>(op, dyn_mu_proj_w, nullptr, nullptr, dyn_mu, out_mu, Nn, Dk, Dk);

    // 7) ctrl = silu([o, velocity] @ ctrl_in_w + b)
    gemm_kernel<1, true><<<dim3(CHc / 64, Nn / 64), 256>>>(op, ctrl_in_w, velocity, ctrl_in_w + (size_t)Dk * CHc, ctrl_in_b, ctrl, Nn, CHc, Dk);

    // 8) co = ctrl @ ctrl_out_w + b
    gemm_kernel<0, false><<<dim3(3 * Dk / 64, Nn / 64), 256>>>(ctrl, ctrl_out_w, nullptr, nullptr, ctrl_out_b, co, Nn, 3 * Dk, CHc);

    // 9) dynamics: v_next (output), hidden2
    dynamics_kernel<<<(Nn * Dk / 4 + 255) / 256, 256>>>((const float4*)hidden, (const float4*)velocity,
                                                        (const float4*)op, (const float4*)out_mu, co,
                                                        (float4*)out_v, (float4*)h2);

    // 10) rmsnorm2
    rmsnorm_kernel<<<Nn, 256>>>(h2, ln2_w, x2);

    // 11) router
    reset_counts_kernel<<<1, 32>>>();
    router_kernel<<<(Nn * 32 + 255) / 256, 256>>>(out_mu, mu_router_w, token_ids);

    // 12) MoE gate/up fused
    moe_gateup_kernel<<<dim3(Ff / 64, Nn / 64, Ee), 256>>>(x2, w_gate, w_up, mid);

    // 13) MoE down + residual -> final hidden (output)
    moe_down_kernel<<<dim3(Dk / 64, Nn / 64, Ee), 256>>>(mid, w_down, h2, out_hidden);
}